// round 7
// baseline (speedup 1.0000x reference)
#include <cuda_runtime.h>
#include <cuda_fp16.h>
#include <cstdint>

// Problem constants
#define BATCH 32
#define TT    4096
#define HH    256
#define TB    (TT * BATCH)     // 131072 rows of enc
#define NCTAS (TB / 64)        // 2048 energy CTAs
#define FIRST_SM (NCTAS - BATCH)

// -------------------- scratch (static device arrays) -----------------------
__device__ float g_pre1[BATCH * HH];            // W1*hidden + bias
__device__ float g_scores[BATCH * TT];          // transposed scores [b][t]
__device__ unsigned char g_bpk[4 * 32768];      // B fp16 pre-swizzled, per chunk
__device__ unsigned int g_done;                 // completion ticket counter

// -------------------- helpers ----------------------------------------------
__device__ __forceinline__ uint32_t smem_u32(const void* p) {
    uint32_t a;
    asm("{ .reg .u64 t; cvta.to.shared.u64 t, %1; cvt.u32.u64 %0, t; }" : "=r"(a) : "l"(p));
    return a;
}
__device__ __forceinline__ void cp16(void* smem_dst, const void* gsrc) {
    unsigned s = (unsigned)__cvta_generic_to_shared(smem_dst);
    asm volatile("cp.async.cg.shared.global [%0], [%1], 16;\n" :: "r"(s), "l"(gsrc));
}
#define CP_COMMIT() asm volatile("cp.async.commit_group;\n" ::: "memory")
#define CP_WAIT0()  asm volatile("cp.async.wait_group 0;\n" ::: "memory")
#define CP_WAIT1()  asm volatile("cp.async.wait_group 1;\n" ::: "memory")

__device__ __forceinline__ uint32_t pack_f16x2(float x, float y) {
    uint32_t r;
    asm("cvt.rn.f16x2.f32 %0, %1, %2;" : "=r"(r) : "f"(y), "f"(x));
    return r;
}
__device__ __forceinline__ void ldsm4(uint32_t* r, uint32_t addr) {
    asm volatile("ldmatrix.sync.aligned.m8n8.x4.shared.b16 {%0,%1,%2,%3}, [%4];"
                 : "=r"(r[0]), "=r"(r[1]), "=r"(r[2]), "=r"(r[3]) : "r"(addr));
}
__device__ __forceinline__ void mma16816(float* c, const uint32_t* a, uint32_t b0, uint32_t b1) {
    asm volatile("mma.sync.aligned.m16n8k16.row.col.f32.f16.f16.f32 "
                 "{%0,%1,%2,%3}, {%4,%5,%6,%7}, {%8,%9}, {%0,%1,%2,%3};"
                 : "+f"(c[0]), "+f"(c[1]), "+f"(c[2]), "+f"(c[3])
                 : "r"(a[0]), "r"(a[1]), "r"(a[2]), "r"(a[3]), "r"(b0), "r"(b1));
}

// ---------------------------------------------------------------------------
// Kernel 1 (fused init): blocks [0,1024) pre1, [1024,1280) bpack. Zeros g_done.
// ---------------------------------------------------------------------------
__global__ void init_kernel(const float* __restrict__ hidden,
                            const float* __restrict__ attn_w,
                            const float* __restrict__ attn_b) {
    if (blockIdx.x == 0 && threadIdx.x == 0) g_done = 0u;
    if (blockIdx.x < 1024) {
        int gw   = (blockIdx.x * 256 + threadIdx.x) >> 5;   // 0..8191
        int lane = threadIdx.x & 31;
        int b = gw >> 8, h = gw & 255;
        const float4* hp = (const float4*)(hidden + (size_t)b * HH);
        const float4* wp = (const float4*)(attn_w + (size_t)h * (2 * HH));
        float4 x0 = hp[lane],      w0 = wp[lane];
        float4 x1 = hp[lane + 32], w1 = wp[lane + 32];
        float s = x0.x*w0.x + x0.y*w0.y + x0.z*w0.z + x0.w*w0.w
                + x1.x*w1.x + x1.y*w1.y + x1.z*w1.z + x1.w*w1.w;
        #pragma unroll
        for (int o = 16; o; o >>= 1) s += __shfl_xor_sync(0xffffffffu, s, o);
        if (lane == 0) g_pre1[gw] = s + attn_b[h];
    } else {
        int idx = (blockIdx.x - 1024) * 256 + threadIdx.x;  // 0..65535
        int c = idx >> 14;
        int r = idx & 16383;
        int n = r >> 6;
        int k = r & 63;
        float val = attn_w[(size_t)n * 512 + 256 + c * 64 + k];
        __half hv = __float2half_rn(val);
        uint32_t o  = (uint32_t)(k * 2) ^ ((uint32_t)(n & 7) * 16);
        uint32_t so = (uint32_t)n * 128 + o;
        *(uint16_t*)(g_bpk + c * 32768 + so) = __half_as_ushort(hv);
    }
}

// ---------------------------------------------------------------------------
// Kernel 2: fp16 HMMA GEMM + fused epilogue + fused (ticketed) softmax.
// CTA: 64 rows x 256 cols, 256 thr (8 warps, 2x4), warp tile 32x64, occ 2.
// SMEM: As 3 x [64][64] fp16 = 24KB @ 0
//       Bs 2 x [256][64] fp16 = 64KB @ 24576       (88KB total)
// ---------------------------------------------------------------------------
#define A_BUF(i) ((uint32_t)(i) * 8192u)
#define B_BUF(i) (24576u + (uint32_t)(i) * 32768u)
#define SMEM_DYN 90112

__global__ __launch_bounds__(256, 2)
void energy_kernel(const float* __restrict__ enc, const float* __restrict__ v,
                   float* __restrict__ out) {
    extern __shared__ __align__(1024) unsigned char smem[];
    const uint32_t sb = smem_u32(smem);
    const int tid = threadIdx.x, wid = tid >> 5, L = tid & 31;
    const int wm = wid >> 2, wn = wid & 3;
    const int r0 = blockIdx.x * 64;

    float acc[2][8][4];
    #pragma unroll
    for (int i = 0; i < 2; i++)
        #pragma unroll
        for (int j = 0; j < 8; j++)
            #pragma unroll
            for (int q = 0; q < 4; q++) acc[i][j][q] = 0.f;

    float4 a_st[2][2];

    auto ldg_A = [&](int c) {
        #pragma unroll
        for (int it = 0; it < 2; it++) {
            int idx = tid + it * 256;          // 0..511
            int row = idx >> 3, c8 = idx & 7;
            const float4* p = (const float4*)(enc + (size_t)(r0 + row) * HH + c * 64 + c8 * 8);
            a_st[it][0] = p[0];
            a_st[it][1] = p[1];
        }
    };
    auto sts_A = [&](int buf) {
        #pragma unroll
        for (int it = 0; it < 2; it++) {
            int idx = tid + it * 256;
            int row = idx >> 3, c8 = idx & 7;
            uint4 hv = make_uint4(pack_f16x2(a_st[it][0].x, a_st[it][0].y),
                                  pack_f16x2(a_st[it][0].z, a_st[it][0].w),
                                  pack_f16x2(a_st[it][1].x, a_st[it][1].y),
                                  pack_f16x2(a_st[it][1].z, a_st[it][1].w));
            uint32_t off = (uint32_t)row * 128 + (((uint32_t)c8 * 16) ^ ((uint32_t)(row & 7) * 16));
            *(uint4*)(smem + A_BUF(buf) + off) = hv;
        }
    };
    auto cpy_B = [&](int buf, int c) {
        #pragma unroll
        for (int st = 0; st < 8; st++) {
            int off = (tid + st * 256) * 16;
            cp16(smem + B_BUF(buf) + off, g_bpk + c * 32768 + off);
        }
        CP_COMMIT();
    };

    const int lrow16 = L & 15;
    const uint32_t lcol = (uint32_t)(L >> 4) * 16;

    auto mma_chunk = [&](int abuf, int bbuf) {
        const uint32_t aB = sb + A_BUF(abuf);
        const uint32_t bB = sb + B_BUF(bbuf);
        #pragma unroll
        for (int ks = 0; ks < 4; ks++) {
            const uint32_t kb = (uint32_t)ks * 32;
            uint32_t ah[2][4], bf[4][4];
            #pragma unroll
            for (int mi = 0; mi < 2; mi++) {
                int arow = wm * 32 + mi * 16 + lrow16;
                uint32_t aoff = (uint32_t)arow * 128 + ((kb + lcol) ^ ((uint32_t)(arow & 7) * 16));
                ldsm4(ah[mi], aB + aoff);
            }
            #pragma unroll
            for (int ni2 = 0; ni2 < 4; ni2++) {
                int brow = wn * 64 + ni2 * 16 + lrow16;
                uint32_t boff = (uint32_t)brow * 128 + ((kb + lcol) ^ ((uint32_t)(brow & 7) * 16));
                ldsm4(bf[ni2], bB + boff);
            }
            #pragma unroll
            for (int ni2 = 0; ni2 < 4; ni2++)
                #pragma unroll
                for (int mi = 0; mi < 2; mi++) {
                    mma16816(acc[mi][ni2 * 2 + 0], ah[mi], bf[ni2][0], bf[ni2][2]);
                    mma16816(acc[mi][ni2 * 2 + 1], ah[mi], bf[ni2][1], bf[ni2][3]);
                }
        }
    };

    // ---- prologue ----
    ldg_A(0);
    cpy_B(0, 0);                 // group0: B0
    sts_A(0);
    ldg_A(1);
    cpy_B(1, 1);                 // group1: B1
    CP_WAIT1();                  // B0 done (B1 may be in flight)
    __syncthreads();

    // ---- mainloop: A buf = c%3, B buf = c%2 ----
    // c=0
    sts_A(1); ldg_A(2);
    mma_chunk(0, 0);
    __syncthreads();             // frees B buf0; A buf1 visible
    cpy_B(0, 2);                 // group2: B2 into freed buf0
    CP_WAIT1();                  // B1 done
    // c=1
    sts_A(2); ldg_A(3);
    mma_chunk(1, 1);
    __syncthreads();
    cpy_B(1, 3);                 // group3: B3
    CP_WAIT1();                  // B2 done
    // c=2
    sts_A(0);
    mma_chunk(2, 0);
    __syncthreads();
    CP_WAIT0();                  // B3 done
    // c=3
    mma_chunk(0, 1);
    __syncthreads();             // all warps done reading smem before epilogue reuse

    // ---- epilogue: +pre1, relu, dot v, reduce, transposed store ----
    float* pre1s = (float*)smem;                   // [32][257] = 32896B
    float* vs    = (float*)(smem + 32896);         // [256]
    float* ps    = (float*)(smem + 33920);         // [64][4]
    #pragma unroll
    for (int i = 0; i < 32; i++) {
        int idx = tid + i * 256;                   // 0..8191
        int bb = idx >> 8, cc = idx & 255;
        pre1s[bb * 257 + cc] = g_pre1[idx];
    }
    vs[tid] = v[tid];
    __syncthreads();

    #pragma unroll
    for (int mi = 0; mi < 2; mi++) {
        #pragma unroll
        for (int p = 0; p < 2; p++) {
            int row = wm * 32 + mi * 16 + (L >> 2) + p * 8;   // 0..63
            int bb  = row & 31;
            float s = 0.f;
            #pragma unroll
            for (int ni = 0; ni < 8; ni++) {
                int n0 = wn * 64 + ni * 8 + (L & 3) * 2;
                float e0 = acc[mi][ni][p * 2 + 0] + pre1s[bb * 257 + n0];
                float e1 = acc[mi][ni][p * 2 + 1] + pre1s[bb * 257 + n0 + 1];
                s += fmaxf(e0, 0.f) * vs[n0] + fmaxf(e1, 0.f) * vs[n0 + 1];
            }
            s += __shfl_xor_sync(0xffffffffu, s, 1);
            s += __shfl_xor_sync(0xffffffffu, s, 2);
            if ((L & 3) == 0) ps[row * 4 + wn] = s;
        }
    }
    __syncthreads();
    if (tid < 64) {
        float tot = ps[tid * 4] + ps[tid * 4 + 1] + ps[tid * 4 + 2] + ps[tid * 4 + 3];
        g_scores[(size_t)(tid & 31) * TT + blockIdx.x * 2 + (tid >> 5)] = tot;
    }

    // ---- ticketed softmax: last BATCH CTAs each handle one row ----
    __threadfence();
    __shared__ unsigned int ticket_s;
    __syncthreads();                               // scores stored by tid<64 first
    if (tid == 0) ticket_s = atomicAdd(&g_done, 1u);
    __syncthreads();
    unsigned int ticket = ticket_s;
    if (ticket < FIRST_SM) return;

    int row = (int)(ticket - FIRST_SM);            // 0..31
    if (tid == 0) {
        while (atomicAdd(&g_done, 0u) < (unsigned)NCTAS) __nanosleep(64);
    }
    __syncthreads();
    __threadfence();

    const float4* sc4 = (const float4*)(g_scores + (size_t)row * TT);
    float4 x[4];
    #pragma unroll
    for (int i = 0; i < 4; i++) x[i] = sc4[tid + i * 256];

    float* red = (float*)smem;                     // 8 floats
    float* bcp = (float*)smem + 8;

    float m = -1e30f;
    #pragma unroll
    for (int i = 0; i < 4; i++)
        m = fmaxf(m, fmaxf(fmaxf(x[i].x, x[i].y), fmaxf(x[i].z, x[i].w)));
    #pragma unroll
    for (int o = 16; o; o >>= 1) m = fmaxf(m, __shfl_xor_sync(0xffffffffu, m, o));
    if (L == 0) red[wid] = m;
    __syncthreads();
    if (tid < 8) {
        float t = red[tid];
        #pragma unroll
        for (int o = 4; o; o >>= 1) t = fmaxf(t, __shfl_xor_sync(0xffu, t, o));
        if (tid == 0) bcp[0] = t;
    }
    __syncthreads();
    m = bcp[0];

    float e[4][4];
    float ssum = 0.f;
    #pragma unroll
    for (int i = 0; i < 4; i++) {
        e[i][0] = expf(x[i].x - m); e[i][1] = expf(x[i].y - m);
        e[i][2] = expf(x[i].z - m); e[i][3] = expf(x[i].w - m);
        ssum += (e[i][0] + e[i][1]) + (e[i][2] + e[i][3]);
    }
    #pragma unroll
    for (int o = 16; o; o >>= 1) ssum += __shfl_xor_sync(0xffffffffu, ssum, o);
    if (L == 0) red[wid] = ssum;
    __syncthreads();
    if (tid < 8) {
        float t = red[tid];
        #pragma unroll
        for (int o = 4; o; o >>= 1) t += __shfl_xor_sync(0xffu, t, o);
        if (tid == 0) bcp[0] = 1.f / t;
    }
    __syncthreads();
    float inv = bcp[0];

    float4* ob4 = (float4*)(out + (size_t)row * TT);
    #pragma unroll
    for (int i = 0; i < 4; i++)
        ob4[tid + i * 256] = make_float4(e[i][0] * inv, e[i][1] * inv,
                                         e[i][2] * inv, e[i][3] * inv);
}

// ---------------------------------------------------------------------------
extern "C" void kernel_launch(void* const* d_in, const int* in_sizes, int n_in,
                              void* d_out, int out_size) {
    const float* hidden = (const float*)d_in[0];   // [B, H]
    const float* enc    = (const float*)d_in[1];   // [T, B, H]
    const float* attn_w = (const float*)d_in[2];   // [H, 2H]
    const float* attn_b = (const float*)d_in[3];   // [H]
    const float* v      = (const float*)d_in[4];   // [H]
    float* out = (float*)d_out;                    // [B, 1, T]

    cudaFuncSetAttribute(energy_kernel,
                         cudaFuncAttributeMaxDynamicSharedMemorySize, SMEM_DYN);

    init_kernel<<<1280, 256>>>(hidden, attn_w, attn_b);
    energy_kernel<<<NCTAS, 256, SMEM_DYN>>>(enc, v, out);
}